// round 5
// baseline (speedup 1.0000x reference)
#include <cuda_runtime.h>
#include <cstdio>

// ---------------- problem constants ----------------
#define BB 8
#define S1C 256
#define M2C 129
#define PLANE (S1C*M2C)            // 33024
#define N0 (BB*32*PLANE)           // 8454144 complex (xs0 / skip0)
#define N1 (BB*64*128*64)          // 4194304 complex (skip1)
#define N2 (BB*64*64*32)           // 1048576 complex (skip2)
#define OFF_SKIP0 (N0)             // output float offsets (real parts only)
#define OFF_SKIP1 (2*N0)
#define OFF_SKIP2 (2*N0+N1)
#define TOTAL_F32 (2*N0+N1+N2)     // 22151168 floats == out_size

// complex scratch in device globals (exonerated in R3)
__device__ float2 g_x1_0[N0];      // x1_0; real part mutated by up1 -> final xs0/skip0 (real)
__device__ float2 g_x1_1[N1];      // x1_1; mutated by up2 -> final skip1
__device__ float2 g_sk2[N2];       // skip2

__device__ __forceinline__ float gelu1(float v){
    float u  = 0.7978845608028654f * (v + 0.044715f * v * v * v);
    float au = fabsf(u);
    float e  = __expf(2.0f * au);
    float t  = 1.0f - 2.0f / (e + 1.0f);
    t = (u < 0.0f) ? -t : t;
    return 0.5f * v * (1.0f + t);
}

__device__ __forceinline__ void kpow3(float kv, float* r0, float* i0,
                                      float* r1, float* i1, float* r2, float* i2){
    float a  = fabsf(kv);
    float c1 = cbrtf(a);
    float c2 = c1 * c1;
    if (kv >= 0.0f){
        *r0 = c1;        *i0 = 0.0f;
        *r1 = c2;        *i1 = 0.0f;
        *r2 = a;         *i2 = 0.0f;
    } else {
        *r0 =  0.5f*c1;  *i0 = 0.86602540f*c1;
        *r1 = -0.5f*c2;  *i1 = 0.86602540f*c2;
        *r2 = -a;        *i2 = 0.0f;
    }
}

// ---------------- K1: fused level-0 -> g_x1_0 ----------------
__global__ void __launch_bounds__(128)
k_level0(const float* __restrict__ xr, const float* __restrict__ xi,
         const float* __restrict__ Re,
         const float* __restrict__ w1r, const float* __restrict__ w1i,
         const float* __restrict__ b1r, const float* __restrict__ b1i,
         const float* __restrict__ w2r, const float* __restrict__ w2i,
         const float* __restrict__ b2r, const float* __restrict__ b2i,
         const float* __restrict__ w0r, const float* __restrict__ w0i)
{
    __shared__ float2 sw1[288], sw2[1024], sw0[1024], sb1[32], sb2[32];
    for (int t = threadIdx.x; t < 288; t += 128) sw1[t] = make_float2(w1r[t], w1i[t]);
    for (int t = threadIdx.x; t < 1024; t += 128){
        sw2[t] = make_float2(w2r[t], w2i[t]);
        sw0[t] = make_float2(w0r[t], w0i[t]);
    }
    if (threadIdx.x < 32){
        sb1[threadIdx.x] = make_float2(b1r[threadIdx.x], b1i[threadIdx.x]);
        sb2[threadIdx.x] = make_float2(b2r[threadIdx.x], b2i[threadIdx.x]);
    }
    __syncthreads();

    int p = blockIdx.x * 128 + threadIdx.x;     // 264192 exactly
    int b   = p / PLANE;
    int sp  = p - b * PLANE;
    int s1v = sp / M2C;
    int m2v = sp - s1v * M2C;

    int xoffi = b * 32 * PLANE + sp;
    if ((unsigned)xoffi > (unsigned)(N0 - 1 - 31*PLANE) || (unsigned)b > 7u){
        printf("OOB k_level0 p=%d\n", p); return;
    }

    float fr[9], fi[9];
    {
        float kv = (s1v < 128) ? (float)s1v : (float)(s1v - 256);
        kpow3(kv, &fr[0], &fi[0], &fr[2], &fi[2], &fr[4], &fi[4]);
    }
    {
        float kv = (m2v < 128) ? (float)m2v : -128.0f;
        kpow3(kv, &fr[1], &fi[1], &fr[3], &fi[3], &fr[5], &fi[5]);
    }
    {
        float r = Re[b];
        float c1 = cbrtf(r);
        fr[6] = c1; fr[7] = c1 * c1; fr[8] = r;
        fi[6] = 0.f; fi[7] = 0.f; fi[8] = 0.f;
    }

    float hr[32], hi[32];
#pragma unroll
    for (int o = 0; o < 32; o++){
        float ar = sb1[o].x, ai = sb1[o].y;
#pragma unroll
        for (int i = 0; i < 9; i++){
            float2 w = sw1[o*9 + i];
            ar += fr[i]*w.x - fi[i]*w.y;
            ai += fr[i]*w.y + fi[i]*w.x;
        }
        hr[o] = gelu1(ar);
        hi[o] = gelu1(ai);
    }

    float qr[32], qi[32];
#pragma unroll
    for (int o = 0; o < 32; o++){
        float ar = sb2[o].x, ai = sb2[o].y;
#pragma unroll
        for (int i = 0; i < 32; i++){
            float2 w = sw2[o*32 + i];
            ar += hr[i]*w.x - hi[i]*w.y;
            ai += hr[i]*w.y + hi[i]*w.x;
        }
        float vr = xr[xoffi + o*PLANE];
        float vi = xi[xoffi + o*PLANE];
        float zr = vr*ar - vi*ai;
        float zi = vr*ai + vi*ar;
        bool keep = sqrtf(zr*zr + zi*zi) > 0.05f;
        qr[o] = (keep ? zr : 0.0f) + 1.0f;
        qi[o] =  keep ? zi : 0.0f;
    }

    for (int o = 0; o < 32; o++){
        float ar = 0.0f, ai = 0.0f;
#pragma unroll
        for (int i = 0; i < 32; i++){
            float2 w = sw0[i*32 + o];
            ar += qr[i]*w.x - qi[i]*w.y;
            ai += qr[i]*w.y + qi[i]*w.x;
        }
        g_x1_0[xoffi + o*PLANE] = make_float2(gelu1(ar), gelu1(ai));
    }
}

// ---------------- K2: down level 1 (32 -> 64) -> g_x1_1 ----------------
__global__ void __launch_bounds__(128)
k_down1(const float* __restrict__ wr_g, const float* __restrict__ wi_g)
{
    __shared__ float2 sw[2048];
    for (int t = threadIdx.x; t < 2048; t += 128) sw[t] = make_float2(wr_g[t], wi_g[t]);
    __syncthreads();

    int p = blockIdx.x * 128 + threadIdx.x;     // 65536
    int b = p >> 13;
    int rc = p & 8191;
    int r = rc >> 6;
    int c = rc & 63;
    int srow = (r < 64) ? r : r + 128;
    int src  = b * 32 * PLANE + srow * M2C + c;
    int dst  = b * 64 * 8192 + r * 64 + c;

    if ((unsigned)src > (unsigned)(N0 - 1 - 31*PLANE) ||
        (unsigned)dst > (unsigned)(N1 - 1 - 63*8192)){
        printf("OOB k_down1 p=%d\n", p); return;
    }

    float ur[32], ui[32];
#pragma unroll
    for (int i = 0; i < 32; i++){
        float2 v = g_x1_0[src + i*PLANE];
        ur[i] = v.x; ui[i] = v.y;
    }
    for (int o = 0; o < 64; o++){
        float ar = 0.0f, ai = 0.0f;
#pragma unroll
        for (int i = 0; i < 32; i++){
            float2 w = sw[i*64 + o];
            ar += ur[i]*w.x - ui[i]*w.y;
            ai += ur[i]*w.y + ui[i]*w.x;
        }
        g_x1_1[dst + o*8192] = make_float2(gelu1(ar) + 1.0f, gelu1(ai));
    }
}

// ---------------- K3: down level 2 (64 -> 64) -> g_sk2 ----------------
__global__ void __launch_bounds__(128)
k_down2(const float* __restrict__ wr_g, const float* __restrict__ wi_g)
{
    __shared__ float2 sw[4096];
    for (int t = threadIdx.x; t < 4096; t += 128) sw[t] = make_float2(wr_g[t], wi_g[t]);
    __syncthreads();

    int p = blockIdx.x * 128 + threadIdx.x;     // 16384
    int b = p >> 11;
    int rc = p & 2047;
    int r = rc >> 5;
    int c = rc & 31;
    int srow = (r < 32) ? r : r + 64;
    int src  = b * 64 * 8192 + srow * 64 + c;
    int dst  = b * 64 * 2048 + r * 32 + c;

    if ((unsigned)src > (unsigned)(N1 - 1 - 63*8192) ||
        (unsigned)dst > (unsigned)(N2 - 1 - 63*2048)){
        printf("OOB k_down2 p=%d\n", p); return;
    }

    float ur[64], ui[64];
#pragma unroll
    for (int i = 0; i < 64; i++){
        float2 v = g_x1_1[src + i*8192];
        ur[i] = v.x; ui[i] = v.y;
    }
    for (int o = 0; o < 64; o++){
        float ar = 0.0f, ai = 0.0f;
#pragma unroll
        for (int i = 0; i < 64; i++){
            float2 w = sw[i*64 + o];
            ar += ur[i]*w.x - ui[i]*w.y;
            ai += ur[i]*w.y + ui[i]*w.x;
        }
        g_sk2[dst + o*2048] = make_float2(gelu1(ar) + 1.0f, gelu1(ai));
    }
}

// ---------------- K4: up level 2 (add cgelu(sk2 @ Wu2) into g_x1_1 corners) ----------------
__global__ void __launch_bounds__(128)
k_up2(const float* __restrict__ wr_g, const float* __restrict__ wi_g)
{
    __shared__ float2 sw[4096];
    for (int t = threadIdx.x; t < 4096; t += 128) sw[t] = make_float2(wr_g[t], wi_g[t]);
    __syncthreads();

    int p = blockIdx.x * 128 + threadIdx.x;     // 16384
    int b = p >> 11;
    int rc = p & 2047;
    int r = rc >> 5;
    int c = rc & 31;
    int src  = b * 64 * 2048 + r * 32 + c;
    int srow = (r < 32) ? r : r + 64;
    int dst  = b * 64 * 8192 + srow * 64 + c;

    if ((unsigned)src > (unsigned)(N2 - 1 - 63*2048) ||
        (unsigned)dst > (unsigned)(N1 - 1 - 63*8192)){
        printf("OOB k_up2 p=%d\n", p); return;
    }

    float ur[64], ui[64];
#pragma unroll
    for (int i = 0; i < 64; i++){
        float2 v = g_sk2[src + i*2048];
        ur[i] = v.x; ui[i] = v.y;
    }
    for (int o = 0; o < 64; o++){
        float ar = 0.0f, ai = 0.0f;
#pragma unroll
        for (int i = 0; i < 64; i++){
            float2 w = sw[i*64 + o];
            ar += ur[i]*w.x - ui[i]*w.y;
            ai += ur[i]*w.y + ui[i]*w.x;
        }
        float2 old = g_x1_1[dst + o*8192];
        g_x1_1[dst + o*8192] = make_float2(old.x + gelu1(ar), old.y + gelu1(ai));
    }
}

// ---------------- K5: up level 1 (real-only accumulate into g_x1_0) ----------------
__global__ void __launch_bounds__(128)
k_up1(const float* __restrict__ wr_g, const float* __restrict__ wi_g)
{
    __shared__ float2 sw[2048];
    for (int t = threadIdx.x; t < 2048; t += 128) sw[t] = make_float2(wr_g[t], wi_g[t]);
    __syncthreads();

    int p = blockIdx.x * 128 + threadIdx.x;     // 65536
    int b = p >> 13;
    int rc = p & 8191;
    int r = rc >> 6;
    int c = rc & 63;
    int src  = b * 64 * 8192 + r * 64 + c;
    int drow = (r < 64) ? r : r + 128;
    int dst  = b * 32 * PLANE + drow * M2C + c;

    if ((unsigned)src > (unsigned)(N1 - 1 - 63*8192) ||
        (unsigned)dst > (unsigned)(N0 - 1 - 31*PLANE)){
        printf("OOB k_up1 p=%d\n", p); return;
    }

    float ur[64], ui[64];
#pragma unroll
    for (int i = 0; i < 64; i++){
        float2 v = g_x1_1[src + i*8192];        // final skip1 (post up2)
        ur[i] = v.x; ui[i] = v.y;
    }
    for (int o = 0; o < 32; o++){
        float ar = 0.0f;                        // real part only: imag never consumed
#pragma unroll
        for (int i = 0; i < 64; i++){
            float2 w = sw[i*32 + o];
            ar += ur[i]*w.x - ui[i]*w.y;
        }
        g_x1_0[dst + o*PLANE].x += gelu1(ar);
    }
}

// ---------------- K6: finalize — write real parts into d_out (float32) ----------------
__global__ void k_finalize(float* __restrict__ out)
{
    int idx = blockIdx.x * blockDim.x + threadIdx.x;
    if (idx >= TOTAL_F32) return;
    float v;
    if (idx < N0)                 v = g_x1_0[idx].x;
    else if (idx < 2*N0)          v = g_x1_0[idx - N0].x;
    else if (idx < OFF_SKIP2)     v = g_x1_1[idx - OFF_SKIP1].x;
    else                          v = g_sk2 [idx - OFF_SKIP2].x;
    out[idx] = v;
}

// ---------------- launch ----------------
extern "C" void kernel_launch(void* const* d_in, const int* in_sizes, int n_in,
                              void* d_out, int out_size)
{
    const float* xr   = (const float*)d_in[0];
    const float* xi   = (const float*)d_in[1];
    const float* Re   = (const float*)d_in[2];
    const float* w1r  = (const float*)d_in[3];
    const float* w1i  = (const float*)d_in[4];
    const float* b1r  = (const float*)d_in[5];
    const float* b1i  = (const float*)d_in[6];
    const float* w2r  = (const float*)d_in[7];
    const float* w2i  = (const float*)d_in[8];
    const float* b2r  = (const float*)d_in[9];
    const float* b2i  = (const float*)d_in[10];
    const float* w0r  = (const float*)d_in[11];
    const float* w0i  = (const float*)d_in[12];
    const float* wd1r = (const float*)d_in[13];
    const float* wd1i = (const float*)d_in[14];
    const float* wu1r = (const float*)d_in[15];
    const float* wu1i = (const float*)d_in[16];
    const float* wd2r = (const float*)d_in[17];
    const float* wd2i = (const float*)d_in[18];
    const float* wu2r = (const float*)d_in[19];
    const float* wu2i = (const float*)d_in[20];

    k_level0<<<(BB*PLANE)/128, 128>>>(xr, xi, Re,
                                      w1r, w1i, b1r, b1i,
                                      w2r, w2i, b2r, b2i,
                                      w0r, w0i);
    k_down1<<<65536/128, 128>>>(wd1r, wd1i);
    k_down2<<<16384/128, 128>>>(wd2r, wd2i);
    k_up2  <<<16384/128, 128>>>(wu2r, wu2i);
    k_up1  <<<65536/128, 128>>>(wu1r, wu1i);
    k_finalize<<<(TOTAL_F32 + 255)/256, 256>>>((float*)d_out);
}

// round 6
// speedup vs baseline: 1.5263x; 1.5263x over previous
#include <cuda_runtime.h>

// ---------------- problem constants ----------------
#define BB 8
#define S1C 256
#define M2C 129
#define PLANE (S1C*M2C)            // 33024
#define N0 (BB*32*PLANE)           // 8454144
#define N1 (BB*64*128*64)          // 4194304
#define N2 (BB*64*64*32)           // 1048576
#define OFF_SKIP0 (N0)
#define OFF_SKIP1 (2*N0)
#define OFF_SKIP2 (2*N0+N1)

// complex scratch
__device__ float2 g_x1_0[N0];      // level-0 complex activation (read by down1)
__device__ float2 g_x1_1[N1];      // level-1 complex activation (mutated by up2, read by up1)
__device__ float2 g_sk2[N2];       // skip2 complex

__device__ __forceinline__ float gelu1(float v){
    // tanh-approx gelu via MUFU.TANH (1 MUFU op; no divide, no exp)
    float u = 0.7978845608028654f * v * fmaf(0.044715f * v, v, 1.0f);
    float t;
    asm("tanh.approx.f32 %0, %1;" : "=f"(t) : "f"(u));
    return 0.5f * v * (1.0f + t);
}

__device__ __forceinline__ void kpow3(float kv, float* r0, float* i0,
                                      float* r1, float* i1, float* r2, float* i2){
    float a  = fabsf(kv);
    float c1 = cbrtf(a);
    float c2 = c1 * c1;
    if (kv >= 0.0f){
        *r0 = c1;        *i0 = 0.0f;
        *r1 = c2;        *i1 = 0.0f;
        *r2 = a;         *i2 = 0.0f;
    } else {
        *r0 =  0.5f*c1;  *i0 = 0.86602540f*c1;
        *r1 = -0.5f*c2;  *i1 = 0.86602540f*c2;
        *r2 = -a;        *i2 = 0.0f;
    }
}

// ---------------- K1: fused level-0 (2 threads/pixel, 16 ch each) ----------------
__global__ void __launch_bounds__(128)
k_level0(const float* __restrict__ xr, const float* __restrict__ xi,
         const float* __restrict__ Re,
         const float* __restrict__ w1r, const float* __restrict__ w1i,
         const float* __restrict__ b1r, const float* __restrict__ b1i,
         const float* __restrict__ w2r, const float* __restrict__ w2i,
         const float* __restrict__ b2r, const float* __restrict__ b2i,
         const float* __restrict__ w0r, const float* __restrict__ w0i,
         float* __restrict__ out)
{
    __shared__ float2 sw1[288], sw2[1024], sw0[1024], sb1[32], sb2[32];
    __shared__ float2 hq[32*64];                       // h then q exchange buffer
    for (int t = threadIdx.x; t < 288; t += 128) sw1[t] = make_float2(w1r[t], w1i[t]);
    for (int t = threadIdx.x; t < 1024; t += 128){
        sw2[t] = make_float2(w2r[t], w2i[t]);
        sw0[t] = make_float2(w0r[t], w0i[t]);
    }
    if (threadIdx.x < 32){
        sb1[threadIdx.x] = make_float2(b1r[threadIdx.x], b1i[threadIdx.x]);
        sb2[threadIdx.x] = make_float2(b2r[threadIdx.x], b2i[threadIdx.x]);
    }
    __syncthreads();

    int t    = threadIdx.x;
    int px   = t & 63;
    int half = t >> 6;
    int ob   = half * 16;
    int p    = blockIdx.x * 64 + px;                   // 264192 = 4128*64 exactly
    int b    = p / PLANE;
    int sp   = p - b * PLANE;
    int s1v  = sp / M2C;
    int m2v  = sp - s1v * M2C;
    int xoffi = b * 32 * PLANE + sp;

    float fr[9], fi[9];
    {
        float kv = (s1v < 128) ? (float)s1v : (float)(s1v - 256);
        kpow3(kv, &fr[0], &fi[0], &fr[2], &fi[2], &fr[4], &fi[4]);
    }
    {
        float kv = (m2v < 128) ? (float)m2v : -128.0f;
        kpow3(kv, &fr[1], &fi[1], &fr[3], &fi[3], &fr[5], &fi[5]);
    }
    {
        float r = Re[b];
        float c1 = cbrtf(r);
        fr[6] = c1; fr[7] = c1 * c1; fr[8] = r;
        fi[6] = 0.f; fi[7] = 0.f; fi[8] = 0.f;
    }

    // layer 1: 9 -> 32 (this thread's 16), cgelu -> smem
#pragma unroll
    for (int oo = 0; oo < 16; oo++){
        int o = ob + oo;
        float ar = sb1[o].x, ai = sb1[o].y;
#pragma unroll
        for (int i = 0; i < 9; i++){
            float2 w = sw1[o*9 + i];
            ar += fr[i]*w.x - fi[i]*w.y;
            ai += fr[i]*w.y + fi[i]*w.x;
        }
        hq[o*64 + px] = make_float2(gelu1(ar), gelu1(ai));
    }
    __syncthreads();

    float hr[32], hi[32];
#pragma unroll
    for (int i = 0; i < 32; i++){
        float2 v = hq[i*64 + px];
        hr[i] = v.x; hi[i] = v.y;
    }
    __syncthreads();                                   // all reads done before overwrite

    // layer 2: 32 -> 32 (16 here); fuse x*rf, squared mask, +1 -> smem (reuse hq)
    float qr[16], qi[16];
#pragma unroll
    for (int oo = 0; oo < 16; oo++){
        int o = ob + oo;
        float ar = sb2[o].x, ai = sb2[o].y;
#pragma unroll
        for (int i = 0; i < 32; i++){
            float2 w = sw2[o*32 + i];
            ar += hr[i]*w.x - hi[i]*w.y;
            ai += hr[i]*w.y + hi[i]*w.x;
        }
        float vr = xr[xoffi + o*PLANE];
        float vi = xi[xoffi + o*PLANE];
        float zr = vr*ar - vi*ai;
        float zi = vr*ai + vi*ar;
        bool keep = (zr*zr + zi*zi) > 0.0025f;         // == |z| > 0.05
        qr[oo] = (keep ? zr : 0.0f) + 1.0f;
        qi[oo] =  keep ? zi : 0.0f;
    }
#pragma unroll
    for (int oo = 0; oo < 16; oo++)
        hq[(ob + oo)*64 + px] = make_float2(qr[oo], qi[oo]);
    __syncthreads();

#pragma unroll
    for (int i = 0; i < 32; i++){
        float2 v = hq[i*64 + px];
        hr[i] = v.x; hi[i] = v.y;
    }

    // layer 3: W0 ('io'), cgelu -> g_x1_0 complex + out real (region0 & skip0)
#pragma unroll
    for (int oo = 0; oo < 16; oo++){
        int o = ob + oo;
        float ar = 0.0f, ai = 0.0f;
#pragma unroll
        for (int i = 0; i < 32; i++){
            float2 w = sw0[i*32 + o];
            ar += hr[i]*w.x - hi[i]*w.y;
            ai += hr[i]*w.y + hi[i]*w.x;
        }
        float gr = gelu1(ar), gi = gelu1(ai);
        int idx = xoffi + o*PLANE;
        g_x1_0[idx] = make_float2(gr, gi);
        out[idx] = gr;
        out[OFF_SKIP0 + idx] = gr;
    }
}

// ---------------- K2: down1 (32->64), 32 px/block, 8 out/thread ----------------
__global__ void __launch_bounds__(256)
k_down1(const float* __restrict__ wr_g, const float* __restrict__ wi_g,
        float* __restrict__ out)
{
    __shared__ float2 sw[2048];                 // wd1 (32,64) 'io'
    __shared__ float2 in_s[32*32];              // [i][pb]
    for (int t = threadIdx.x; t < 2048; t += 256) sw[t] = make_float2(wr_g[t], wi_g[t]);

    int p0 = blockIdx.x * 32;                   // 65536/32 = 2048 blocks
    for (int k = threadIdx.x; k < 1024; k += 256){
        int pb = k & 31, i = k >> 5;
        int p = p0 + pb;
        int b = p >> 13, rc = p & 8191, r = rc >> 6, c = rc & 63;
        int srow = (r < 64) ? r : r + 128;
        in_s[i*32 + pb] = g_x1_0[b*32*PLANE + srow*M2C + c + i*PLANE];
    }
    __syncthreads();

    int pb = threadIdx.x & 31, og = threadIdx.x >> 5;
    int p = p0 + pb;
    int b = p >> 13, rc = p & 8191, r = rc >> 6, c = rc & 63;
    int dst = b * 64 * 8192 + r * 64 + c;

    float accr[8], acci[8];
#pragma unroll
    for (int k = 0; k < 8; k++){ accr[k] = 0.f; acci[k] = 0.f; }
#pragma unroll 4
    for (int i = 0; i < 32; i++){
        float2 u = in_s[i*32 + pb];
#pragma unroll
        for (int k = 0; k < 8; k++){
            float2 w = sw[i*64 + og*8 + k];
            accr[k] += u.x*w.x - u.y*w.y;
            acci[k] += u.x*w.y + u.y*w.x;
        }
    }
#pragma unroll
    for (int k = 0; k < 8; k++){
        int o = og*8 + k;
        float gr = gelu1(accr[k]) + 1.0f;
        float gi = gelu1(acci[k]);
        g_x1_1[dst + o*8192] = make_float2(gr, gi);
        out[OFF_SKIP1 + dst + o*8192] = gr;
    }
}

// ---------------- K3: down2 (64->64), 32 px/block, 8 out/thread ----------------
__global__ void __launch_bounds__(256)
k_down2(const float* __restrict__ wr_g, const float* __restrict__ wi_g,
        float* __restrict__ out)
{
    __shared__ float2 sw[4096];                 // wd2 (64,64) 'io'  (32KB)
    __shared__ float2 in_s[64*32];              // 16KB
    for (int t = threadIdx.x; t < 4096; t += 256) sw[t] = make_float2(wr_g[t], wi_g[t]);

    int p0 = blockIdx.x * 32;                   // 16384/32 = 512 blocks
    for (int k = threadIdx.x; k < 2048; k += 256){
        int pb = k & 31, i = k >> 5;
        int p = p0 + pb;
        int b = p >> 11, rc = p & 2047, r = rc >> 5, c = rc & 31;
        int srow = (r < 32) ? r : r + 64;
        in_s[i*32 + pb] = g_x1_1[b*64*8192 + srow*64 + c + i*8192];
    }
    __syncthreads();

    int pb = threadIdx.x & 31, og = threadIdx.x >> 5;
    int p = p0 + pb;
    int b = p >> 11, rc = p & 2047, r = rc >> 5, c = rc & 31;
    int dst = b * 64 * 2048 + r * 32 + c;

    float accr[8], acci[8];
#pragma unroll
    for (int k = 0; k < 8; k++){ accr[k] = 0.f; acci[k] = 0.f; }
#pragma unroll 4
    for (int i = 0; i < 64; i++){
        float2 u = in_s[i*32 + pb];
#pragma unroll
        for (int k = 0; k < 8; k++){
            float2 w = sw[i*64 + og*8 + k];
            accr[k] += u.x*w.x - u.y*w.y;
            acci[k] += u.x*w.y + u.y*w.x;
        }
    }
#pragma unroll
    for (int k = 0; k < 8; k++){
        int o = og*8 + k;
        float gr = gelu1(accr[k]) + 1.0f;
        float gi = gelu1(acci[k]);
        g_sk2[dst + o*2048] = make_float2(gr, gi);
        out[OFF_SKIP2 + dst + o*2048] = gr;
    }
}

// ---------------- K4: up2 (64->64), add into g_x1_1 corners + out skip1 ----------------
__global__ void __launch_bounds__(256)
k_up2(const float* __restrict__ wr_g, const float* __restrict__ wi_g,
      float* __restrict__ out)
{
    __shared__ float2 sw[4096];                 // wu2 (64,64) 'io'
    __shared__ float2 in_s[64*32];
    for (int t = threadIdx.x; t < 4096; t += 256) sw[t] = make_float2(wr_g[t], wi_g[t]);

    int p0 = blockIdx.x * 32;                   // 512 blocks
    for (int k = threadIdx.x; k < 2048; k += 256){
        int pb = k & 31, i = k >> 5;
        int p = p0 + pb;
        int b = p >> 11, rc = p & 2047, r = rc >> 5, c = rc & 31;
        in_s[i*32 + pb] = g_sk2[b*64*2048 + r*32 + c + i*2048];
    }
    __syncthreads();

    int pb = threadIdx.x & 31, og = threadIdx.x >> 5;
    int p = p0 + pb;
    int b = p >> 11, rc = p & 2047, r = rc >> 5, c = rc & 31;
    int srow = (r < 32) ? r : r + 64;
    int dst = b * 64 * 8192 + srow * 64 + c;

    float accr[8], acci[8];
#pragma unroll
    for (int k = 0; k < 8; k++){ accr[k] = 0.f; acci[k] = 0.f; }
#pragma unroll 4
    for (int i = 0; i < 64; i++){
        float2 u = in_s[i*32 + pb];
#pragma unroll
        for (int k = 0; k < 8; k++){
            float2 w = sw[i*64 + og*8 + k];
            accr[k] += u.x*w.x - u.y*w.y;
            acci[k] += u.x*w.y + u.y*w.x;
        }
    }
#pragma unroll
    for (int k = 0; k < 8; k++){
        int o = og*8 + k;
        float2 old = g_x1_1[dst + o*8192];
        float nr = old.x + gelu1(accr[k]);
        float ni = old.y + gelu1(acci[k]);
        g_x1_1[dst + o*8192] = make_float2(nr, ni);
        out[OFF_SKIP1 + dst + o*8192] = nr;
    }
}

// ---------------- K5: up1 (64->32, real-only), add into out region0 + skip0 ----------------
__global__ void __launch_bounds__(256)
k_up1(const float* __restrict__ wr_g, const float* __restrict__ wi_g,
      float* __restrict__ out)
{
    __shared__ float2 sw[2048];                 // wu1 (64,32) 'io'
    __shared__ float2 in_s[64*32];
    for (int t = threadIdx.x; t < 2048; t += 256) sw[t] = make_float2(wr_g[t], wi_g[t]);

    int p0 = blockIdx.x * 32;                   // 65536/32 = 2048 blocks
    for (int k = threadIdx.x; k < 2048; k += 256){
        int pb = k & 31, i = k >> 5;
        int p = p0 + pb;
        int b = p >> 13, rc = p & 8191, r = rc >> 6, c = rc & 63;
        in_s[i*32 + pb] = g_x1_1[b*64*8192 + r*64 + c + i*8192];   // final skip1
    }
    __syncthreads();

    int pb = threadIdx.x & 31, og = threadIdx.x >> 5;   // og 0..7, 4 outputs each
    int p = p0 + pb;
    int b = p >> 13, rc = p & 8191, r = rc >> 6, c = rc & 63;
    int drow = (r < 64) ? r : r + 128;
    int dst = b * 32 * PLANE + drow * M2C + c;

    float accr[4];
#pragma unroll
    for (int k = 0; k < 4; k++) accr[k] = 0.f;
#pragma unroll 4
    for (int i = 0; i < 64; i++){
        float2 u = in_s[i*32 + pb];
#pragma unroll
        for (int k = 0; k < 4; k++){
            float2 w = sw[i*32 + og*4 + k];
            accr[k] += u.x*w.x - u.y*w.y;      // real part only: imag never consumed
        }
    }
#pragma unroll
    for (int k = 0; k < 4; k++){
        int o = og*4 + k;
        float v = out[dst + o*PLANE] + gelu1(accr[k]);
        out[dst + o*PLANE] = v;
        out[OFF_SKIP0 + dst + o*PLANE] = v;
    }
}

// ---------------- launch ----------------
extern "C" void kernel_launch(void* const* d_in, const int* in_sizes, int n_in,
                              void* d_out, int out_size)
{
    const float* xr   = (const float*)d_in[0];
    const float* xi   = (const float*)d_in[1];
    const float* Re   = (const float*)d_in[2];
    const float* w1r  = (const float*)d_in[3];
    const float* w1i  = (const float*)d_in[4];
    const float* b1r  = (const float*)d_in[5];
    const float* b1i  = (const float*)d_in[6];
    const float* w2r  = (const float*)d_in[7];
    const float* w2i  = (const float*)d_in[8];
    const float* b2r  = (const float*)d_in[9];
    const float* b2i  = (const float*)d_in[10];
    const float* w0r  = (const float*)d_in[11];
    const float* w0i  = (const float*)d_in[12];
    const float* wd1r = (const float*)d_in[13];
    const float* wd1i = (const float*)d_in[14];
    const float* wu1r = (const float*)d_in[15];
    const float* wu1i = (const float*)d_in[16];
    const float* wd2r = (const float*)d_in[17];
    const float* wd2i = (const float*)d_in[18];
    const float* wu2r = (const float*)d_in[19];
    const float* wu2i = (const float*)d_in[20];

    float* out = (float*)d_out;

    k_level0<<<(BB*PLANE)/64, 128>>>(xr, xi, Re,
                                     w1r, w1i, b1r, b1i,
                                     w2r, w2i, b2r, b2i,
                                     w0r, w0i, out);
    k_down1<<<2048, 256>>>(wd1r, wd1i, out);
    k_down2<<<512,  256>>>(wd2r, wd2i, out);
    k_up2  <<<512,  256>>>(wu2r, wu2i, out);
    k_up1  <<<2048, 256>>>(wu1r, wu1i, out);
}

// round 7
// speedup vs baseline: 2.1847x; 1.4314x over previous
#include <cuda_runtime.h>

typedef unsigned long long ull;

// ---------------- problem constants ----------------
#define BB 8
#define S1C 256
#define M2C 129
#define PLANE (S1C*M2C)            // 33024
#define N0 (BB*32*PLANE)           // 8454144
#define N1 (BB*64*128*64)          // 4194304
#define N2 (BB*64*64*32)           // 1048576
#define OFF_SKIP0 (N0)
#define OFF_SKIP1 (2*N0)
#define OFF_SKIP2 (2*N0+N1)

// complex scratch
__device__ float2 g_x1_0[N0];
__device__ float2 g_x1_1[N1];
__device__ float2 g_sk2[N2];
// level-0 layer-1 separable tables: pre-act = A(s1) + B(m2) + C(b)
__device__ float2 g_tabA[256*32];
__device__ float2 g_tabB[129*32];
__device__ float2 g_tabC[8*32];

// ---------------- packed f32x2 helpers ----------------
__device__ __forceinline__ ull pk(float x, float y){
    ull r; asm("mov.b64 %0, {%1,%2};" : "=l"(r) : "f"(x), "f"(y)); return r;
}
__device__ __forceinline__ void upk(ull v, float& x, float& y){
    asm("mov.b64 {%0,%1}, %2;" : "=f"(x), "=f"(y) : "l"(v));
}
__device__ __forceinline__ void ffma2(ull& d, ull a, ull b){
    asm("fma.rn.f32x2 %0, %1, %2, %0;" : "+l"(d) : "l"(a), "l"(b));
}

__device__ __forceinline__ float gelu1(float v){
    float u = 0.7978845608028654f * v * fmaf(0.044715f * v, v, 1.0f);
    float t;
    asm("tanh.approx.f32 %0, %1;" : "=f"(t) : "f"(u));
    return 0.5f * v * (1.0f + t);
}

__device__ __forceinline__ void kpow3(float kv, float* r0, float* i0,
                                      float* r1, float* i1, float* r2, float* i2){
    float a  = fabsf(kv);
    float c1 = cbrtf(a);
    float c2 = c1 * c1;
    if (kv >= 0.0f){
        *r0 = c1;        *i0 = 0.0f;
        *r1 = c2;        *i1 = 0.0f;
        *r2 = a;         *i2 = 0.0f;
    } else {
        *r0 =  0.5f*c1;  *i0 = 0.86602540f*c1;
        *r1 = -0.5f*c2;  *i1 = 0.86602540f*c2;
        *r2 = -a;        *i2 = 0.0f;
    }
}

__device__ __forceinline__ float2 cmul(float2 a, float br, float bi){
    return make_float2(a.x*br - a.y*bi, a.x*bi + a.y*br);
}

// ---------------- K0: prep separable layer-1 tables ----------------
__global__ void k_prep(const float* __restrict__ Re,
                       const float* __restrict__ w1r, const float* __restrict__ w1i,
                       const float* __restrict__ b1r, const float* __restrict__ b1i)
{
    int idx = blockIdx.x * 256 + threadIdx.x;
    if (idx < 8192){                                    // A[s1][o]
        int s1 = idx >> 5, o = idx & 31;
        float kv = (s1 < 128) ? (float)s1 : (float)(s1 - 256);
        float f0r,f0i,f1r,f1i,f2r,f2i;
        kpow3(kv, &f0r,&f0i, &f1r,&f1i, &f2r,&f2i);
        float2 a = make_float2(0,0);
        float2 w;
        w = make_float2(w1r[o*9+0], w1i[o*9+0]); a.x += w.x*f0r - w.y*f0i; a.y += w.x*f0i + w.y*f0r;
        w = make_float2(w1r[o*9+2], w1i[o*9+2]); a.x += w.x*f1r - w.y*f1i; a.y += w.x*f1i + w.y*f1r;
        w = make_float2(w1r[o*9+4], w1i[o*9+4]); a.x += w.x*f2r - w.y*f2i; a.y += w.x*f2i + w.y*f2r;
        g_tabA[idx] = a;
    } else if (idx < 8192 + 4128){                      // B[m2][o]
        int j = idx - 8192;
        int m2 = j / 32, o = j % 32;
        float kv = (m2 < 128) ? (float)m2 : -128.0f;
        float f0r,f0i,f1r,f1i,f2r,f2i;
        kpow3(kv, &f0r,&f0i, &f1r,&f1i, &f2r,&f2i);
        float2 a = make_float2(0,0);
        float2 w;
        w = make_float2(w1r[o*9+1], w1i[o*9+1]); a.x += w.x*f0r - w.y*f0i; a.y += w.x*f0i + w.y*f0r;
        w = make_float2(w1r[o*9+3], w1i[o*9+3]); a.x += w.x*f1r - w.y*f1i; a.y += w.x*f1i + w.y*f1r;
        w = make_float2(w1r[o*9+5], w1i[o*9+5]); a.x += w.x*f2r - w.y*f2i; a.y += w.x*f2i + w.y*f2r;
        g_tabB[j] = a;
    } else if (idx < 8192 + 4128 + 256){                // C[b][o]
        int j = idx - 8192 - 4128;
        int b = j >> 5, o = j & 31;
        float r = Re[b];
        float c1 = cbrtf(r), c2 = c1*c1;
        float2 a = make_float2(b1r[o], b1i[o]);
        a.x += w1r[o*9+6]*c1; a.y += w1i[o*9+6]*c1;
        a.x += w1r[o*9+7]*c2; a.y += w1i[o*9+7]*c2;
        a.x += w1r[o*9+8]*r;  a.y += w1i[o*9+8]*r;
        g_tabC[j] = a;
    }
}

// ---------------- K1: fused level-0 (4 threads/pixel, 8 outputs each) ----------------
__global__ void __launch_bounds__(256)
k_level0(const float* __restrict__ xr, const float* __restrict__ xi,
         const float* __restrict__ w2r, const float* __restrict__ w2i,
         const float* __restrict__ b2r, const float* __restrict__ b2i,
         const float* __restrict__ w0r, const float* __restrict__ w0i,
         float* __restrict__ out)
{
    __shared__ float2 sw2[1024];      // w2 (o*32+i)
    __shared__ float2 sw0[1024];      // w0 (i*32+o)
    __shared__ float2 hq[32*64];      // h / q exchange, [ch][px]

    for (int t = threadIdx.x; t < 1024; t += 256){
        sw2[t] = make_float2(w2r[t], w2i[t]);
        sw0[t] = make_float2(w0r[t], w0i[t]);
    }

    int t    = threadIdx.x;
    int px   = t & 63;
    int ob   = (t >> 6) * 8;          // 0,8,16,24
    int p    = blockIdx.x * 64 + px;  // 264192 = 4128*64
    int b    = p / PLANE;
    int sp   = p - b * PLANE;
    int s1v  = sp / M2C;
    int m2v  = sp - s1v * M2C;
    int xoffi = b * 32 * PLANE + sp;

    // layer 1 via tables
#pragma unroll
    for (int oo = 0; oo < 8; oo++){
        int o = ob + oo;
        float2 A = g_tabA[s1v*32 + o];
        float2 B = g_tabB[m2v*32 + o];
        float2 C = g_tabC[b*32 + o];
        hq[o*64 + px] = make_float2(gelu1(A.x + B.x + C.x), gelu1(A.y + B.y + C.y));
    }
    __syncthreads();

    const ull* sw2u = (const ull*)sw2;
    const ull* sw0u = (const ull*)sw0;

    // layer 2: 32->32, dual-accumulator f32x2
    ull a1[8], a2[8];
#pragma unroll
    for (int oo = 0; oo < 8; oo++){
        a1[oo] = pk(b2r[ob+oo], b2i[ob+oo]);
        a2[oo] = 0ull;
    }
#pragma unroll 4
    for (int i = 0; i < 32; i++){
        float2 h = hq[i*64 + px];
        ull hr2 = pk(h.x, h.x), hi2 = pk(h.y, h.y);
#pragma unroll
        for (int oo = 0; oo < 8; oo++){
            ull w = sw2u[(ob+oo)*32 + i];
            ffma2(a1[oo], hr2, w);
            ffma2(a2[oo], hi2, w);
        }
    }
    float qr[8], qi[8];
#pragma unroll
    for (int oo = 0; oo < 8; oo++){
        float p1,q1,r1,s1;
        upk(a1[oo], p1, q1);
        upk(a2[oo], r1, s1);
        float ar = p1 - s1;               // re_feature real
        float ai = q1 + r1;               // re_feature imag
        int o = ob + oo;
        float vr = xr[xoffi + o*PLANE];
        float vi = xi[xoffi + o*PLANE];
        float zr = vr*ar - vi*ai;
        float zi = vr*ai + vi*ar;
        bool keep = (zr*zr + zi*zi) > 0.0025f;
        qr[oo] = (keep ? zr : 0.0f) + 1.0f;
        qi[oo] =  keep ? zi : 0.0f;
    }
    __syncthreads();
#pragma unroll
    for (int oo = 0; oo < 8; oo++)
        hq[(ob+oo)*64 + px] = make_float2(qr[oo], qi[oo]);
    __syncthreads();

    // layer 3: W0 ('io'), f32x2
#pragma unroll
    for (int oo = 0; oo < 8; oo++){ a1[oo] = 0ull; a2[oo] = 0ull; }
#pragma unroll 4
    for (int i = 0; i < 32; i++){
        float2 q = hq[i*64 + px];
        ull ur2 = pk(q.x, q.x), ui2 = pk(q.y, q.y);
#pragma unroll
        for (int oo = 0; oo < 8; oo++){
            ull w = sw0u[i*32 + ob + oo];
            ffma2(a1[oo], ur2, w);
            ffma2(a2[oo], ui2, w);
        }
    }
#pragma unroll
    for (int oo = 0; oo < 8; oo++){
        float p1,q1,r1,s1;
        upk(a1[oo], p1, q1);
        upk(a2[oo], r1, s1);
        float gr = gelu1(p1 - s1);
        float gi = gelu1(q1 + r1);
        int idx = xoffi + (ob+oo)*PLANE;
        g_x1_0[idx] = make_float2(gr, gi);
        out[idx] = gr;
        out[OFF_SKIP0 + idx] = gr;
    }
}

// ---------------- K2: down1 (32->64) ----------------
__global__ void __launch_bounds__(256)
k_down1(const float* __restrict__ wr_g, const float* __restrict__ wi_g,
        float* __restrict__ out)
{
    __shared__ float2 sw[2048];        // wd1 (i*64+o)
    __shared__ float2 in_s[1024];      // [i][pb]
    for (int t = threadIdx.x; t < 2048; t += 256) sw[t] = make_float2(wr_g[t], wi_g[t]);

    int p0 = blockIdx.x * 32;          // 2048 blocks
    for (int k = threadIdx.x; k < 1024; k += 256){
        int pb = k & 31, i = k >> 5;
        int p = p0 + pb;
        int b = p >> 13, rc = p & 8191, r = rc >> 6, c = rc & 63;
        int srow = (r < 64) ? r : r + 128;
        in_s[k] = g_x1_0[b*32*PLANE + srow*M2C + c + i*PLANE];
    }
    __syncthreads();

    const ull* swu = (const ull*)sw;
    int pb = threadIdx.x & 31, og = threadIdx.x >> 5;
    int p = p0 + pb;
    int b = p >> 13, rc = p & 8191, r = rc >> 6, c = rc & 63;
    int dst = b * 64 * 8192 + r * 64 + c;

    ull a1[8], a2[8];
#pragma unroll
    for (int k = 0; k < 8; k++){ a1[k] = 0ull; a2[k] = 0ull; }
#pragma unroll 4
    for (int i = 0; i < 32; i++){
        float2 u = in_s[i*32 + pb];
        ull ur = pk(u.x, u.x), ui = pk(u.y, u.y);
#pragma unroll
        for (int k = 0; k < 8; k++){
            ull w = swu[i*64 + og*8 + k];
            ffma2(a1[k], ur, w);
            ffma2(a2[k], ui, w);
        }
    }
#pragma unroll
    for (int k = 0; k < 8; k++){
        float p1,q1,r1,s1;
        upk(a1[k], p1, q1);
        upk(a2[k], r1, s1);
        int o = og*8 + k;
        float gr = gelu1(p1 - s1) + 1.0f;
        float gi = gelu1(q1 + r1);
        g_x1_1[dst + o*8192] = make_float2(gr, gi);
        out[OFF_SKIP1 + dst + o*8192] = gr;
    }
}

// ---------------- K3: down2 (64->64) ----------------
__global__ void __launch_bounds__(256)
k_down2(const float* __restrict__ wr_g, const float* __restrict__ wi_g,
        float* __restrict__ out)
{
    __shared__ float2 sw[4096];        // 32KB
    __shared__ float2 in_s[2048];      // 16KB (total 48KB exactly)
    for (int t = threadIdx.x; t < 4096; t += 256) sw[t] = make_float2(wr_g[t], wi_g[t]);

    int p0 = blockIdx.x * 32;          // 512 blocks
    for (int k = threadIdx.x; k < 2048; k += 256){
        int pb = k & 31, i = k >> 5;
        int p = p0 + pb;
        int b = p >> 11, rc = p & 2047, r = rc >> 5, c = rc & 31;
        int srow = (r < 32) ? r : r + 64;
        in_s[k] = g_x1_1[b*64*8192 + srow*64 + c + i*8192];
    }
    __syncthreads();

    const ull* swu = (const ull*)sw;
    int pb = threadIdx.x & 31, og = threadIdx.x >> 5;
    int p = p0 + pb;
    int b = p >> 11, rc = p & 2047, r = rc >> 5, c = rc & 31;
    int dst = b * 64 * 2048 + r * 32 + c;

    ull a1[8], a2[8];
#pragma unroll
    for (int k = 0; k < 8; k++){ a1[k] = 0ull; a2[k] = 0ull; }
#pragma unroll 4
    for (int i = 0; i < 64; i++){
        float2 u = in_s[i*32 + pb];
        ull ur = pk(u.x, u.x), ui = pk(u.y, u.y);
#pragma unroll
        for (int k = 0; k < 8; k++){
            ull w = swu[i*64 + og*8 + k];
            ffma2(a1[k], ur, w);
            ffma2(a2[k], ui, w);
        }
    }
#pragma unroll
    for (int k = 0; k < 8; k++){
        float p1,q1,r1,s1;
        upk(a1[k], p1, q1);
        upk(a2[k], r1, s1);
        int o = og*8 + k;
        float gr = gelu1(p1 - s1) + 1.0f;
        float gi = gelu1(q1 + r1);
        g_sk2[dst + o*2048] = make_float2(gr, gi);
        out[OFF_SKIP2 + dst + o*2048] = gr;
    }
}

// ---------------- K4: up2 (64->64, accumulate into g_x1_1) ----------------
__global__ void __launch_bounds__(256)
k_up2(const float* __restrict__ wr_g, const float* __restrict__ wi_g,
      float* __restrict__ out)
{
    __shared__ float2 sw[4096];
    __shared__ float2 in_s[2048];
    for (int t = threadIdx.x; t < 4096; t += 256) sw[t] = make_float2(wr_g[t], wi_g[t]);

    int p0 = blockIdx.x * 32;          // 512 blocks
    for (int k = threadIdx.x; k < 2048; k += 256){
        int pb = k & 31, i = k >> 5;
        int p = p0 + pb;
        int b = p >> 11, rc = p & 2047, r = rc >> 5, c = rc & 31;
        in_s[k] = g_sk2[b*64*2048 + r*32 + c + i*2048];
    }
    __syncthreads();

    const ull* swu = (const ull*)sw;
    int pb = threadIdx.x & 31, og = threadIdx.x >> 5;
    int p = p0 + pb;
    int b = p >> 11, rc = p & 2047, r = rc >> 5, c = rc & 31;
    int srow = (r < 32) ? r : r + 64;
    int dst = b * 64 * 8192 + srow * 64 + c;

    ull a1[8], a2[8];
#pragma unroll
    for (int k = 0; k < 8; k++){ a1[k] = 0ull; a2[k] = 0ull; }
#pragma unroll 4
    for (int i = 0; i < 64; i++){
        float2 u = in_s[i*32 + pb];
        ull ur = pk(u.x, u.x), ui = pk(u.y, u.y);
#pragma unroll
        for (int k = 0; k < 8; k++){
            ull w = swu[i*64 + og*8 + k];
            ffma2(a1[k], ur, w);
            ffma2(a2[k], ui, w);
        }
    }
#pragma unroll
    for (int k = 0; k < 8; k++){
        float p1,q1,r1,s1;
        upk(a1[k], p1, q1);
        upk(a2[k], r1, s1);
        int o = og*8 + k;
        float2 old = g_x1_1[dst + o*8192];
        float nr = old.x + gelu1(p1 - s1);
        float ni = old.y + gelu1(q1 + r1);
        g_x1_1[dst + o*8192] = make_float2(nr, ni);
        out[OFF_SKIP1 + dst + o*8192] = nr;
    }
}

// ---------------- K5: up1 (64->32, real-only, paired outputs) ----------------
__global__ void __launch_bounds__(256)
k_up1(const float* __restrict__ wr_g, const float* __restrict__ wi_g,
      float* __restrict__ out)
{
    __shared__ ulonglong2 sw4[1024];   // [(i)*16 + opair]: .x=(w0x,w1x) .y=(w0y,w1y)
    __shared__ float2 in_s[2048];
    for (int t = threadIdx.x; t < 1024; t += 256){
        int i = t >> 4, op = t & 15;
        ulonglong2 v;
        v.x = pk(wr_g[i*32 + 2*op], wr_g[i*32 + 2*op + 1]);
        v.y = pk(wi_g[i*32 + 2*op], wi_g[i*32 + 2*op + 1]);
        sw4[t] = v;
    }

    int p0 = blockIdx.x * 32;          // 2048 blocks
    for (int k = threadIdx.x; k < 2048; k += 256){
        int pb = k & 31, i = k >> 5;
        int p = p0 + pb;
        int b = p >> 13, rc = p & 8191, r = rc >> 6, c = rc & 63;
        in_s[k] = g_x1_1[b*64*8192 + r*64 + c + i*8192];   // final skip1
    }
    __syncthreads();

    int pb = threadIdx.x & 31, og = threadIdx.x >> 5;      // 4 outputs = 2 pairs
    int p = p0 + pb;
    int b = p >> 13, rc = p & 8191, r = rc >> 6, c = rc & 63;
    int drow = (r < 64) ? r : r + 128;
    int dst = b * 32 * PLANE + drow * M2C + c;

    ull a1[2] = {0ull, 0ull}, a2[2] = {0ull, 0ull};
#pragma unroll 4
    for (int i = 0; i < 64; i++){
        float2 u = in_s[i*32 + pb];
        ull ur = pk(u.x, u.x), ui = pk(u.y, u.y);
#pragma unroll
        for (int pr = 0; pr < 2; pr++){
            ulonglong2 w = sw4[i*16 + og*2 + pr];
            ffma2(a1[pr], ur, w.x);
            ffma2(a2[pr], ui, w.y);
        }
    }
#pragma unroll
    for (int pr = 0; pr < 2; pr++){
        float x0,x1,y0,y1;
        upk(a1[pr], x0, x1);
        upk(a2[pr], y0, y1);
        int o = og*4 + pr*2;
        float v0 = out[dst + o*PLANE]       + gelu1(x0 - y0);
        float v1 = out[dst + (o+1)*PLANE]   + gelu1(x1 - y1);
        out[dst + o*PLANE] = v0;
        out[OFF_SKIP0 + dst + o*PLANE] = v0;
        out[dst + (o+1)*PLANE] = v1;
        out[OFF_SKIP0 + dst + (o+1)*PLANE] = v1;
    }
}

// ---------------- launch ----------------
extern "C" void kernel_launch(void* const* d_in, const int* in_sizes, int n_in,
                              void* d_out, int out_size)
{
    const float* xr   = (const float*)d_in[0];
    const float* xi   = (const float*)d_in[1];
    const float* Re   = (const float*)d_in[2];
    const float* w1r  = (const float*)d_in[3];
    const float* w1i  = (const float*)d_in[4];
    const float* b1r  = (const float*)d_in[5];
    const float* b1i  = (const float*)d_in[6];
    const float* w2r  = (const float*)d_in[7];
    const float* w2i  = (const float*)d_in[8];
    const float* b2r  = (const float*)d_in[9];
    const float* b2i  = (const float*)d_in[10];
    const float* w0r  = (const float*)d_in[11];
    const float* w0i  = (const float*)d_in[12];
    const float* wd1r = (const float*)d_in[13];
    const float* wd1i = (const float*)d_in[14];
    const float* wu1r = (const float*)d_in[15];
    const float* wu1i = (const float*)d_in[16];
    const float* wd2r = (const float*)d_in[17];
    const float* wd2i = (const float*)d_in[18];
    const float* wu2r = (const float*)d_in[19];
    const float* wu2i = (const float*)d_in[20];

    float* out = (float*)d_out;

    k_prep  <<<51, 256>>>(Re, w1r, w1i, b1r, b1i);
    k_level0<<<4128, 256>>>(xr, xi, w2r, w2i, b2r, b2i, w0r, w0i, out);
    k_down1 <<<2048, 256>>>(wd1r, wd1i, out);
    k_down2 <<<512,  256>>>(wd2r, wd2i, out);
    k_up2   <<<512,  256>>>(wu2r, wu2i, out);
    k_up1   <<<2048, 256>>>(wu1r, wu1i, out);
}

// round 9
// speedup vs baseline: 2.3044x; 1.0548x over previous
#include <cuda_runtime.h>

typedef unsigned long long ull;

// ---------------- problem constants ----------------
#define BB 8
#define S1C 256
#define M2C 129
#define PLANE (S1C*M2C)            // 33024
#define N0 (BB*32*PLANE)           // 8454144
#define N1 (BB*64*128*64)          // 4194304
#define N2 (BB*64*64*32)           // 1048576
#define OFF_SKIP0 (N0)
#define OFF_SKIP1 (2*N0)
#define OFF_SKIP2 (2*N0+N1)

// complex scratch (16B-aligned for vector access)
__device__ __align__(16) float2 g_x1_0[N0];
__device__ __align__(16) float2 g_x1_1[N1];
__device__ __align__(16) float2 g_sk2[N2];
// level-0 layer-1 separable tables: pre-act = A(s1) + B(m2) + C(b)
__device__ float2 g_tabA[256*32];
__device__ float2 g_tabB[129*32];
__device__ float2 g_tabC[8*32];

// ---------------- packed f32x2 helpers ----------------
__device__ __forceinline__ ull pk(float x, float y){
    ull r; asm("mov.b64 %0, {%1,%2};" : "=l"(r) : "f"(x), "f"(y)); return r;
}
__device__ __forceinline__ void upk(ull v, float& x, float& y){
    asm("mov.b64 {%0,%1}, %2;" : "=f"(x), "=f"(y) : "l"(v));
}
__device__ __forceinline__ void ffma2(ull& d, ull a, ull b){
    asm("fma.rn.f32x2 %0, %1, %2, %0;" : "+l"(d) : "l"(a), "l"(b));
}

__device__ __forceinline__ float gelu1(float v){
    float u = 0.7978845608028654f * v * fmaf(0.044715f * v, v, 1.0f);
    float t;
    asm("tanh.approx.f32 %0, %1;" : "=f"(t) : "f"(u));
    return 0.5f * v * (1.0f + t);
}

__device__ __forceinline__ void kpow3(float kv, float* r0, float* i0,
                                      float* r1, float* i1, float* r2, float* i2){
    float a  = fabsf(kv);
    float c1 = cbrtf(a);
    float c2 = c1 * c1;
    if (kv >= 0.0f){
        *r0 = c1;        *i0 = 0.0f;
        *r1 = c2;        *i1 = 0.0f;
        *r2 = a;         *i2 = 0.0f;
    } else {
        *r0 =  0.5f*c1;  *i0 = 0.86602540f*c1;
        *r1 = -0.5f*c2;  *i1 = 0.86602540f*c2;
        *r2 = -a;        *i2 = 0.0f;
    }
}

// ---------------- K0: prep separable layer-1 tables ----------------
__global__ void k_prep(const float* __restrict__ Re,
                       const float* __restrict__ w1r, const float* __restrict__ w1i,
                       const float* __restrict__ b1r, const float* __restrict__ b1i)
{
    int idx = blockIdx.x * 256 + threadIdx.x;
    if (idx < 8192){                                    // A[s1][o]
        int s1 = idx >> 5, o = idx & 31;
        float kv = (s1 < 128) ? (float)s1 : (float)(s1 - 256);
        float f0r,f0i,f1r,f1i,f2r,f2i;
        kpow3(kv, &f0r,&f0i, &f1r,&f1i, &f2r,&f2i);
        float2 a = make_float2(0,0);
        float2 w;
        w = make_float2(w1r[o*9+0], w1i[o*9+0]); a.x += w.x*f0r - w.y*f0i; a.y += w.x*f0i + w.y*f0r;
        w = make_float2(w1r[o*9+2], w1i[o*9+2]); a.x += w.x*f1r - w.y*f1i; a.y += w.x*f1i + w.y*f1r;
        w = make_float2(w1r[o*9+4], w1i[o*9+4]); a.x += w.x*f2r - w.y*f2i; a.y += w.x*f2i + w.y*f2r;
        g_tabA[idx] = a;
    } else if (idx < 8192 + 4128){                      // B[m2][o]
        int j = idx - 8192;
        int m2 = j / 32, o = j % 32;
        float kv = (m2 < 128) ? (float)m2 : -128.0f;
        float f0r,f0i,f1r,f1i,f2r,f2i;
        kpow3(kv, &f0r,&f0i, &f1r,&f1i, &f2r,&f2i);
        float2 a = make_float2(0,0);
        float2 w;
        w = make_float2(w1r[o*9+1], w1i[o*9+1]); a.x += w.x*f0r - w.y*f0i; a.y += w.x*f0i + w.y*f0r;
        w = make_float2(w1r[o*9+3], w1i[o*9+3]); a.x += w.x*f1r - w.y*f1i; a.y += w.x*f1i + w.y*f1r;
        w = make_float2(w1r[o*9+5], w1i[o*9+5]); a.x += w.x*f2r - w.y*f2i; a.y += w.x*f2i + w.y*f2r;
        g_tabB[j] = a;
    } else if (idx < 8192 + 4128 + 256){                // C[b][o]
        int j = idx - 8192 - 4128;
        int b = j >> 5, o = j & 31;
        float r = Re[b];
        float c1 = cbrtf(r), c2 = c1*c1;
        float2 a = make_float2(b1r[o], b1i[o]);
        a.x += w1r[o*9+6]*c1; a.y += w1i[o*9+6]*c1;
        a.x += w1r[o*9+7]*c2; a.y += w1i[o*9+7]*c2;
        a.x += w1r[o*9+8]*r;  a.y += w1i[o*9+8]*r;
        g_tabC[j] = a;
    }
}

// ---------------- K1: fused level-0 (128 px/block, 2 px/thread, 8 outs) ----------------
__global__ void __launch_bounds__(256)
k_level0(const float* __restrict__ xr, const float* __restrict__ xi,
         const float* __restrict__ w2r, const float* __restrict__ w2i,
         const float* __restrict__ b2r, const float* __restrict__ b2i,
         const float* __restrict__ w0r, const float* __restrict__ w0i,
         float* __restrict__ out)
{
    __shared__ __align__(16) float2 sw2t[1024];   // w2 transposed to [i*32+o]  8KB
    __shared__ __align__(16) float2 sw0[1024];    // w0 already [i*32+o]        8KB
    __shared__ __align__(16) float2 hq[32*128];   // [ch][px] exchange          32KB

    for (int t = threadIdx.x; t < 1024; t += 256){
        int o = t >> 5, i = t & 31;
        sw2t[i*32 + o] = make_float2(w2r[t], w2i[t]);
        sw0[t]         = make_float2(w0r[t], w0i[t]);
    }

    int tid = threadIdx.x;
    int pr  = tid & 63;               // pixel-pair id
    int ob  = (tid >> 6) * 8;         // 0,8,16,24
    int p0  = blockIdx.x * 128 + 2*pr;
    int b   = p0 / PLANE;
    int sp0 = p0 - b * PLANE;
    int s1a = sp0 / M2C;
    int m2a = sp0 - s1a * M2C;
    int s1b = s1a, m2b = m2a + 1;
    if (m2b == M2C){ m2b = 0; s1b = s1a + 1; }
    int xoff = b * 32 * PLANE + sp0;  // even

    // layer 1 via tables -> hq
#pragma unroll
    for (int oo = 0; oo < 8; oo++){
        int o = ob + oo;
        float2 C  = g_tabC[b*32 + o];
        float2 A0 = g_tabA[s1a*32 + o], B0 = g_tabB[m2a*32 + o];
        float2 A1 = g_tabA[s1b*32 + o], B1 = g_tabB[m2b*32 + o];
        hq[o*128 + 2*pr]     = make_float2(gelu1(A0.x+B0.x+C.x), gelu1(A0.y+B0.y+C.y));
        hq[o*128 + 2*pr + 1] = make_float2(gelu1(A1.x+B1.x+C.x), gelu1(A1.y+B1.y+C.y));
    }
    __syncthreads();

    const ulonglong2* w2u = (const ulonglong2*)sw2t;
    const ulonglong2* w0u = (const ulonglong2*)sw0;

    // layer 2: 32->32
    ull a1[2][8], a2[2][8];
#pragma unroll
    for (int oo = 0; oo < 8; oo++){
        ull bb = pk(b2r[ob+oo], b2i[ob+oo]);
        a1[0][oo] = bb; a1[1][oo] = bb;
        a2[0][oo] = 0ull; a2[1][oo] = 0ull;
    }
#pragma unroll 4
    for (int i = 0; i < 32; i++){
        ulonglong2 uu = *(const ulonglong2*)(hq + i*128 + 2*pr);
        float r0,i0,r1,i1;
        upk(uu.x, r0, i0); upk(uu.y, r1, i1);
        ull ur0 = pk(r0,r0), ui0 = pk(i0,i0), ur1 = pk(r1,r1), ui1 = pk(i1,i1);
#pragma unroll
        for (int j = 0; j < 4; j++){
            ulonglong2 w = w2u[(i*32 + ob)/2 + j];
            ffma2(a1[0][2*j],   ur0, w.x); ffma2(a2[0][2*j],   ui0, w.x);
            ffma2(a1[0][2*j+1], ur0, w.y); ffma2(a2[0][2*j+1], ui0, w.y);
            ffma2(a1[1][2*j],   ur1, w.x); ffma2(a2[1][2*j],   ui1, w.x);
            ffma2(a1[1][2*j+1], ur1, w.y); ffma2(a2[1][2*j+1], ui1, w.y);
        }
    }

    // re_feature -> x*rf -> mask -> +1  (both pixels)
    float qr[2][8], qi[2][8];
    const float2* xr2 = (const float2*)xr;
    const float2* xi2 = (const float2*)xi;
#pragma unroll
    for (int oo = 0; oo < 8; oo++){
        int o = ob + oo;
        float2 vr = xr2[(xoff + o*PLANE) >> 1];
        float2 vi = xi2[(xoff + o*PLANE) >> 1];
        float p1,q1,r1,s1;
        upk(a1[0][oo], p1, q1); upk(a2[0][oo], r1, s1);
        {
            float ar = p1 - s1, ai = q1 + r1;
            float zr = vr.x*ar - vi.x*ai;
            float zi = vr.x*ai + vi.x*ar;
            bool keep = (zr*zr + zi*zi) > 0.0025f;
            qr[0][oo] = (keep ? zr : 0.0f) + 1.0f;
            qi[0][oo] =  keep ? zi : 0.0f;
        }
        upk(a1[1][oo], p1, q1); upk(a2[1][oo], r1, s1);
        {
            float ar = p1 - s1, ai = q1 + r1;
            float zr = vr.y*ar - vi.y*ai;
            float zi = vr.y*ai + vi.y*ar;
            bool keep = (zr*zr + zi*zi) > 0.0025f;
            qr[1][oo] = (keep ? zr : 0.0f) + 1.0f;
            qi[1][oo] =  keep ? zi : 0.0f;
        }
    }
    __syncthreads();
#pragma unroll
    for (int oo = 0; oo < 8; oo++){
        int o = ob + oo;
        hq[o*128 + 2*pr]     = make_float2(qr[0][oo], qi[0][oo]);
        hq[o*128 + 2*pr + 1] = make_float2(qr[1][oo], qi[1][oo]);
    }
    __syncthreads();

    // layer 3: W0 ('io')
#pragma unroll
    for (int oo = 0; oo < 8; oo++){
        a1[0][oo] = 0ull; a1[1][oo] = 0ull;
        a2[0][oo] = 0ull; a2[1][oo] = 0ull;
    }
#pragma unroll 4
    for (int i = 0; i < 32; i++){
        ulonglong2 uu = *(const ulonglong2*)(hq + i*128 + 2*pr);
        float r0,i0,r1,i1;
        upk(uu.x, r0, i0); upk(uu.y, r1, i1);
        ull ur0 = pk(r0,r0), ui0 = pk(i0,i0), ur1 = pk(r1,r1), ui1 = pk(i1,i1);
#pragma unroll
        for (int j = 0; j < 4; j++){
            ulonglong2 w = w0u[(i*32 + ob)/2 + j];
            ffma2(a1[0][2*j],   ur0, w.x); ffma2(a2[0][2*j],   ui0, w.x);
            ffma2(a1[0][2*j+1], ur0, w.y); ffma2(a2[0][2*j+1], ui0, w.y);
            ffma2(a1[1][2*j],   ur1, w.x); ffma2(a2[1][2*j],   ui1, w.x);
            ffma2(a1[1][2*j+1], ur1, w.y); ffma2(a2[1][2*j+1], ui1, w.y);
        }
    }
#pragma unroll
    for (int oo = 0; oo < 8; oo++){
        float p1,q1,r1,s1;
        int idx = xoff + (ob+oo)*PLANE;          // even
        upk(a1[0][oo], p1, q1); upk(a2[0][oo], r1, s1);
        float gr0 = gelu1(p1 - s1), gi0 = gelu1(q1 + r1);
        upk(a1[1][oo], p1, q1); upk(a2[1][oo], r1, s1);
        float gr1 = gelu1(p1 - s1), gi1 = gelu1(q1 + r1);
        ulonglong2 st; st.x = pk(gr0, gi0); st.y = pk(gr1, gi1);
        *(ulonglong2*)(g_x1_0 + idx) = st;
        ((float2*)out)[idx >> 1] = make_float2(gr0, gr1);
        ((float2*)out)[(OFF_SKIP0 + idx) >> 1] = make_float2(gr0, gr1);
    }
}

// ---------------- K2: down1 (32->64), 64 px/block, 2 px/thread ----------------
__global__ void __launch_bounds__(256)
k_down1(const float* __restrict__ wr_g, const float* __restrict__ wi_g,
        float* __restrict__ out)
{
    __shared__ __align__(16) float2 sw[2048];     // wd1 [i*64+o]  16KB
    __shared__ __align__(16) float2 in_s[2048];   // [i][px]       16KB
    for (int t = threadIdx.x; t < 2048; t += 256) sw[t] = make_float2(wr_g[t], wi_g[t]);

    int p0 = blockIdx.x * 64;                     // 1024 blocks
    for (int k = threadIdx.x; k < 2048; k += 256){
        int px = k & 63, i = k >> 6;
        int p = p0 + px;
        int b = p >> 13, r = (p & 8191) >> 6, c = p & 63;
        int srow = (r < 64) ? r : r + 128;
        in_s[i*64 + px] = g_x1_0[b*32*PLANE + srow*M2C + c + i*PLANE];
    }
    __syncthreads();

    const ulonglong2* wu = (const ulonglong2*)sw;
    int pr = threadIdx.x & 31, ob = (threadIdx.x >> 5) * 8;
    int p = p0 + 2*pr;
    int b = p >> 13, r = (p & 8191) >> 6, c = p & 63;
    int dst = b * 64 * 8192 + r * 64 + c;         // even

    ull a1[2][8], a2[2][8];
#pragma unroll
    for (int oo = 0; oo < 8; oo++){
        a1[0][oo]=0ull; a1[1][oo]=0ull; a2[0][oo]=0ull; a2[1][oo]=0ull;
    }
#pragma unroll 4
    for (int i = 0; i < 32; i++){
        ulonglong2 uu = *(const ulonglong2*)(in_s + i*64 + 2*pr);
        float r0,i0,r1,i1;
        upk(uu.x, r0, i0); upk(uu.y, r1, i1);
        ull ur0 = pk(r0,r0), ui0 = pk(i0,i0), ur1 = pk(r1,r1), ui1 = pk(i1,i1);
#pragma unroll
        for (int j = 0; j < 4; j++){
            ulonglong2 w = wu[(i*64 + ob)/2 + j];
            ffma2(a1[0][2*j],   ur0, w.x); ffma2(a2[0][2*j],   ui0, w.x);
            ffma2(a1[0][2*j+1], ur0, w.y); ffma2(a2[0][2*j+1], ui0, w.y);
            ffma2(a1[1][2*j],   ur1, w.x); ffma2(a2[1][2*j],   ui1, w.x);
            ffma2(a1[1][2*j+1], ur1, w.y); ffma2(a2[1][2*j+1], ui1, w.y);
        }
    }
#pragma unroll
    for (int oo = 0; oo < 8; oo++){
        int o = ob + oo;
        float p1,q1,r1,s1;
        upk(a1[0][oo], p1, q1); upk(a2[0][oo], r1, s1);
        float gr0 = gelu1(p1 - s1) + 1.0f, gi0 = gelu1(q1 + r1);
        upk(a1[1][oo], p1, q1); upk(a2[1][oo], r1, s1);
        float gr1 = gelu1(p1 - s1) + 1.0f, gi1 = gelu1(q1 + r1);
        ulonglong2 st; st.x = pk(gr0, gi0); st.y = pk(gr1, gi1);
        *(ulonglong2*)(g_x1_1 + dst + o*8192) = st;
        ((float2*)out)[(OFF_SKIP1 + dst + o*8192) >> 1] = make_float2(gr0, gr1);
    }
}

// ---------------- K3: down2 (64->64), 32 px/block, 2 px/thread ----------------
__global__ void __launch_bounds__(128)
k_down2(const float* __restrict__ wr_g, const float* __restrict__ wi_g,
        float* __restrict__ out)
{
    __shared__ __align__(16) float2 sw[4096];     // 32KB
    __shared__ __align__(16) float2 in_s[2048];   // 16KB
    for (int t = threadIdx.x; t < 4096; t += 128) sw[t] = make_float2(wr_g[t], wi_g[t]);

    int p0 = blockIdx.x * 32;                     // 512 blocks
    for (int k = threadIdx.x; k < 2048; k += 128){
        int px = k & 31, i = k >> 5;
        int p = p0 + px;
        int b = p >> 11, r = (p & 2047) >> 5, c = p & 31;
        int srow = (r < 32) ? r : r + 64;
        in_s[i*32 + px] = g_x1_1[b*64*8192 + srow*64 + c + i*8192];
    }
    __syncthreads();

    const ulonglong2* wu = (const ulonglong2*)sw;
    int pr = threadIdx.x & 15, ob = (threadIdx.x >> 4) * 8;
    int p = p0 + 2*pr;
    int b = p >> 11, r = (p & 2047) >> 5, c = p & 31;
    int dst = b * 64 * 2048 + r * 32 + c;         // even

    ull a1[2][8], a2[2][8];
#pragma unroll
    for (int oo = 0; oo < 8; oo++){
        a1[0][oo]=0ull; a1[1][oo]=0ull; a2[0][oo]=0ull; a2[1][oo]=0ull;
    }
#pragma unroll 4
    for (int i = 0; i < 64; i++){
        ulonglong2 uu = *(const ulonglong2*)(in_s + i*32 + 2*pr);
        float r0,i0,r1,i1;
        upk(uu.x, r0, i0); upk(uu.y, r1, i1);
        ull ur0 = pk(r0,r0), ui0 = pk(i0,i0), ur1 = pk(r1,r1), ui1 = pk(i1,i1);
#pragma unroll
        for (int j = 0; j < 4; j++){
            ulonglong2 w = wu[(i*64 + ob)/2 + j];
            ffma2(a1[0][2*j],   ur0, w.x); ffma2(a2[0][2*j],   ui0, w.x);
            ffma2(a1[0][2*j+1], ur0, w.y); ffma2(a2[0][2*j+1], ui0, w.y);
            ffma2(a1[1][2*j],   ur1, w.x); ffma2(a2[1][2*j],   ui1, w.x);
            ffma2(a1[1][2*j+1], ur1, w.y); ffma2(a2[1][2*j+1], ui1, w.y);
        }
    }
#pragma unroll
    for (int oo = 0; oo < 8; oo++){
        int o = ob + oo;
        float p1,q1,r1,s1;
        upk(a1[0][oo], p1, q1); upk(a2[0][oo], r1, s1);
        float gr0 = gelu1(p1 - s1) + 1.0f, gi0 = gelu1(q1 + r1);
        upk(a1[1][oo], p1, q1); upk(a2[1][oo], r1, s1);
        float gr1 = gelu1(p1 - s1) + 1.0f, gi1 = gelu1(q1 + r1);
        ulonglong2 st; st.x = pk(gr0, gi0); st.y = pk(gr1, gi1);
        *(ulonglong2*)(g_sk2 + dst + o*2048) = st;
        ((float2*)out)[(OFF_SKIP2 + dst + o*2048) >> 1] = make_float2(gr0, gr1);
    }
}

// ---------------- K4: up2 (64->64, accumulate into g_x1_1) ----------------
__global__ void __launch_bounds__(128)
k_up2(const float* __restrict__ wr_g, const float* __restrict__ wi_g,
      float* __restrict__ out)
{
    __shared__ __align__(16) float2 sw[4096];
    __shared__ __align__(16) float2 in_s[2048];
    for (int t = threadIdx.x; t < 4096; t += 128) sw[t] = make_float2(wr_g[t], wi_g[t]);

    int p0 = blockIdx.x * 32;                     // 512 blocks
    for (int k = threadIdx.x; k < 2048; k += 128){
        int px = k & 31, i = k >> 5;
        int p = p0 + px;
        int b = p >> 11, r = (p & 2047) >> 5, c = p & 31;
        in_s[i*32 + px] = g_sk2[b*64*2048 + r*32 + c + i*2048];
    }
    __syncthreads();

    const ulonglong2* wu = (const ulonglong2*)sw;
    int pr = threadIdx.x & 15, ob = (threadIdx.x >> 4) * 8;
    int p = p0 + 2*pr;
    int b = p >> 11, r = (p & 2047) >> 5, c = p & 31;
    int srow = (r < 32) ? r : r + 64;
    int dst = b * 64 * 8192 + srow * 64 + c;      // even

    ull a1[2][8], a2[2][8];
#pragma unroll
    for (int oo = 0; oo < 8; oo++){
        a1[0][oo]=0ull; a1[1][oo]=0ull; a2[0][oo]=0ull; a2[1][oo]=0ull;
    }
#pragma unroll 4
    for (int i = 0; i < 64; i++){
        ulonglong2 uu = *(const ulonglong2*)(in_s + i*32 + 2*pr);
        float r0,i0,r1,i1;
        upk(uu.x, r0, i0); upk(uu.y, r1, i1);
        ull ur0 = pk(r0,r0), ui0 = pk(i0,i0), ur1 = pk(r1,r1), ui1 = pk(i1,i1);
#pragma unroll
        for (int j = 0; j < 4; j++){
            ulonglong2 w = wu[(i*64 + ob)/2 + j];
            ffma2(a1[0][2*j],   ur0, w.x); ffma2(a2[0][2*j],   ui0, w.x);
            ffma2(a1[0][2*j+1], ur0, w.y); ffma2(a2[0][2*j+1], ui0, w.y);
            ffma2(a1[1][2*j],   ur1, w.x); ffma2(a2[1][2*j],   ui1, w.x);
            ffma2(a1[1][2*j+1], ur1, w.y); ffma2(a2[1][2*j+1], ui1, w.y);
        }
    }
#pragma unroll
    for (int oo = 0; oo < 8; oo++){
        int o = ob + oo;
        float p1,q1,r1,s1;
        upk(a1[0][oo], p1, q1); upk(a2[0][oo], r1, s1);
        float u0r = gelu1(p1 - s1), u0i = gelu1(q1 + r1);
        upk(a1[1][oo], p1, q1); upk(a2[1][oo], r1, s1);
        float u1r = gelu1(p1 - s1), u1i = gelu1(q1 + r1);
        ulonglong2 old = *(const ulonglong2*)(g_x1_1 + dst + o*8192);
        float o0r,o0i,o1r,o1i;
        upk(old.x, o0r, o0i); upk(old.y, o1r, o1i);
        float n0r = o0r + u0r, n0i = o0i + u0i;
        float n1r = o1r + u1r, n1i = o1i + u1i;
        ulonglong2 st; st.x = pk(n0r, n0i); st.y = pk(n1r, n1i);
        *(ulonglong2*)(g_x1_1 + dst + o*8192) = st;
        ((float2*)out)[(OFF_SKIP1 + dst + o*8192) >> 1] = make_float2(n0r, n1r);
    }
}

// ---------------- K5: up1 (64->32, real-only, 2 px + output-pair packing) ----------------
__global__ void __launch_bounds__(256)
k_up1(const float* __restrict__ wr_g, const float* __restrict__ wi_g,
      float* __restrict__ out)
{
    __shared__ __align__(16) ulonglong2 sw4[1024];   // [i*16+op] 16KB
    __shared__ __align__(16) float2 in_s[4096];      // [i][px] 64ch x 64px = 32KB (R8 bug fixed)
    for (int t = threadIdx.x; t < 1024; t += 256){
        int i = t >> 4, op = t & 15;
        ulonglong2 v;
        v.x = pk(wr_g[i*32 + 2*op], wr_g[i*32 + 2*op + 1]);
        v.y = pk(wi_g[i*32 + 2*op], wi_g[i*32 + 2*op + 1]);
        sw4[t] = v;
    }

    int p0 = blockIdx.x * 64;                        // 1024 blocks
    for (int k = threadIdx.x; k < 4096; k += 256){
        int px = k & 63, i = k >> 6;                 // i in [0,63] — all 64 channels
        int p = p0 + px;
        int b = p >> 13, r = (p & 8191) >> 6, c = p & 63;
        in_s[i*64 + px] = g_x1_1[b*64*8192 + r*64 + c + i*8192];   // final skip1
    }
    __syncthreads();

    int pr = threadIdx.x & 31, og = threadIdx.x >> 5;  // og: 2 output-pairs (4 outputs)
    int p = p0 + 2*pr;
    int b = p >> 13, r = (p & 8191) >> 6, c = p & 63;
    int drow = (r < 64) ? r : r + 128;
    int dst = b * 32 * PLANE + drow * M2C + c;

    ull a1[2][2] = {{0ull,0ull},{0ull,0ull}};
    ull a2[2][2] = {{0ull,0ull},{0ull,0ull}};
#pragma unroll 4
    for (int i = 0; i < 64; i++){
        ulonglong2 uu = *(const ulonglong2*)(in_s + i*64 + 2*pr);
        float r0,i0,r1,i1;
        upk(uu.x, r0, i0); upk(uu.y, r1, i1);
        ull ur0 = pk(r0,r0), ui0 = pk(i0,i0), ur1 = pk(r1,r1), ui1 = pk(i1,i1);
#pragma unroll
        for (int j = 0; j < 2; j++){
            ulonglong2 w = sw4[i*16 + og*2 + j];
            ffma2(a1[0][j], ur0, w.x); ffma2(a2[0][j], ui0, w.y);
            ffma2(a1[1][j], ur1, w.x); ffma2(a2[1][j], ui1, w.y);
        }
    }
#pragma unroll
    for (int j = 0; j < 2; j++){
        int o = og*4 + 2*j;
        float x0,x1,y0,y1;
        // pixel 0
        upk(a1[0][j], x0, x1); upk(a2[0][j], y0, y1);
        {
            int idx = dst + o*PLANE;
            float v = out[idx] + gelu1(x0 - y0);
            out[idx] = v; out[OFF_SKIP0 + idx] = v;
            idx = dst + (o+1)*PLANE;
            v = out[idx] + gelu1(x1 - y1);
            out[idx] = v; out[OFF_SKIP0 + idx] = v;
        }
        // pixel 1
        upk(a1[1][j], x0, x1); upk(a2[1][j], y0, y1);
        {
            int idx = dst + 1 + o*PLANE;
            float v = out[idx] + gelu1(x0 - y0);
            out[idx] = v; out[OFF_SKIP0 + idx] = v;
            idx = dst + 1 + (o+1)*PLANE;
            v = out[idx] + gelu1(x1 - y1);
            out[idx] = v; out[OFF_SKIP0 + idx] = v;
        }
    }
}

// ---------------- launch ----------------
extern "C" void kernel_launch(void* const* d_in, const int* in_sizes, int n_in,
                              void* d_out, int out_size)
{
    const float* xr   = (const float*)d_in[0];
    const float* xi   = (const float*)d_in[1];
    const float* Re   = (const float*)d_in[2];
    const float* w1r  = (const float*)d_in[3];
    const float* w1i  = (const float*)d_in[4];
    const float* b1r  = (const float*)d_in[5];
    const float* b1i  = (const float*)d_in[6];
    const float* w2r  = (const float*)d_in[7];
    const float* w2i  = (const float*)d_in[8];
    const float* b2r  = (const float*)d_in[9];
    const float* b2i  = (const float*)d_in[10];
    const float* w0r  = (const float*)d_in[11];
    const float* w0i  = (const float*)d_in[12];
    const float* wd1r = (const float*)d_in[13];
    const float* wd1i = (const float*)d_in[14];
    const float* wu1r = (const float*)d_in[15];
    const float* wu1i = (const float*)d_in[16];
    const float* wd2r = (const float*)d_in[17];
    const float* wd2i = (const float*)d_in[18];
    const float* wu2r = (const float*)d_in[19];
    const float* wu2i = (const float*)d_in[20];

    float* out = (float*)d_out;

    k_prep  <<<51, 256>>>(Re, w1r, w1i, b1r, b1i);
    k_level0<<<2064, 256>>>(xr, xi, w2r, w2i, b2r, b2i, w0r, w0i, out);
    k_down1 <<<1024, 256>>>(wd1r, wd1i, out);
    k_down2 <<<512,  128>>>(wd2r, wd2i, out);
    k_up2   <<<512,  128>>>(wu2r, wu2i, out);
    k_up1   <<<1024, 256>>>(wu1r, wu1i, out);
}